// round 5
// baseline (speedup 1.0000x reference)
#include <cuda_runtime.h>

// BoundaryBCELoss: 5x clamped plus-dilation of two masks + BCE vs target, mean-reduced.
// Round 5: (a) occupancy 3->4 CTAs/SM: 5-6 rows/warp (TILE_Y 32, 42 local rows),
// __launch_bounds__(256,4). (b) saturation skip: dilation is monotone and clamped, so
// a cell==1.0f stays 1.0f forever; if ALL cells a warp owns + its halo rows are exactly
// 1.0f, the iteration is an exact no-op for that warp (every 5-neighborhood sums >= 3).
// Integer compare vs 0x3F800000 pattern + __all_sync, sticky across iterations.
// Interior blocks skip iters 3-5; only blocks containing zero padding keep computing.

#define W_IMG 384
#define H_IMG 384
#define N_IMG 64
#define TILE_X 48
#define TILE_Y 32
#define HALO_X 6            // even => column pairs stay 8B-aligned in gmem
#define HALO_Y 5
#define LDIM_X 60           // TILE_X + 2*HALO_X
#define LDIM_Y 42           // TILE_Y + 2*HALO_Y
#define NP 30               // column pairs
#define NW 8                // warps per CTA
#define NTHREADS 256
#define ITERS 5
#define RMAX 6              // max rows per warp band (warps 0,1: 6 rows; 2..7: 5 rows)

typedef unsigned long long u64;
#define ONE2 0x3F8000003F800000ULL

#define ADD_F32X2(o, a, b) \
    asm("add.rn.f32x2 %0, %1, %2;" : "=l"(o) : "l"(a), "l"(b))
#define PACK2(o, lo, hi) \
    asm("mov.b64 %0, {%1, %2};" : "=l"(o) : "f"(lo), "f"(hi))
#define UNPACK2(lo, hi, in) \
    asm("mov.b64 {%0, %1}, %2;" : "=f"(lo), "=f"(hi) : "l"(in))

__global__ void zero_out_kernel(float* out) { *out = 0.0f; }

__global__ __launch_bounds__(NTHREADS, 4) void boundary_bce_fused_kernel(
    const float* __restrict__ hand,
    const float* __restrict__ obj,
    const float* __restrict__ target,
    float* __restrict__ out)
{
    // Boundary-row exchange: [parity][top/bot][warp][pair] -> {a,b} (16B)
    __shared__ __align__(16) u64 xbuf[2][2][NW][NP][2];
    __shared__ float red[NW];

    const int n   = blockIdx.z;
    const int y0  = blockIdx.y * TILE_Y - HALO_Y;
    const int x0  = blockIdx.x * TILE_X - HALO_X;        // even
    const int tid = threadIdx.x;
    const int w   = tid >> 5;
    const int pl  = tid & 31;

    // Row bands over 42 local rows: warps 0,1 -> 6 rows; warps 2..7 -> 5 rows.
    const int r_lo = (w < 2) ? 6 * w : 5 * w + 2;
    const int R    = (w < 2) ? 6 : 5;

    const int  gx       = x0 + 2 * pl;                    // pair {gx, gx+1} fully in or out
    const bool lane_act = (pl < NP);
    const bool col_in   = lane_act && ((unsigned)gx < W_IMG);
    const bool interior = (x0 >= 0) && (y0 >= 0) &&
                          (x0 + LDIM_X <= W_IMG) && (y0 + LDIM_Y <= H_IMG);

    const size_t img = (size_t)n * H_IMG * W_IMG;
    const float* hb = hand + img;
    const float* ob = obj + img;

    // ---- Stage band rows straight into registers (coalesced LDG.64 x2) ----
    u64 ra[RMAX], rb[RMAX];
    #pragma unroll
    for (int i = 0; i < RMAX; i++) { ra[i] = 0; rb[i] = 0; }

    #pragma unroll
    for (int i = 0; i < RMAX; i++) {
        if (i < R) {
            const int gy = y0 + r_lo + i;
            if (col_in && (unsigned)gy < H_IMG) {
                const float2 hh = *(const float2*)(hb + gy * W_IMG + gx);
                const float2 oo = *(const float2*)(ob + gy * W_IMG + gx);
                PACK2(ra[i], hh.x, oo.x);   // col 2pl   : {h, o}
                PACK2(rb[i], hh.y, oo.y);   // col 2pl+1 : {h, o}
            }
        }
    }

    // ---- 5 dilation iterations ----
    bool skip = false;
    #pragma unroll 1
    for (int k = 0; k < ITERS; k++) {
        const int p = k & 1;

        if (lane_act) {
            // publish my (old) top and bottom rows for neighbor warps
            const int bi = R - 1;
            *(ulonglong2*)&xbuf[p][0][w][pl][0] = make_ulonglong2(ra[0], rb[0]);
            *(ulonglong2*)&xbuf[p][1][w][pl][0] = make_ulonglong2(ra[bi], rb[bi]);
        }
        __syncthreads();

        u64 pa = 0, pb = 0, na = 0, nb = 0;
        if (lane_act && w > 0) {
            ulonglong2 v = *(ulonglong2*)&xbuf[p][1][w - 1][pl][0];
            pa = v.x; pb = v.y;
        }
        if (lane_act && w < NW - 1) {
            ulonglong2 v = *(ulonglong2*)&xbuf[p][0][w + 1][pl][0];
            na = v.x; nb = v.y;
        }

        if (!skip) {
            // Saturation check: if every cell I own + received halo rows == 1.0f
            // exactly, this iteration (and all later ones) is a bitwise no-op.
            bool ok = true;
            #pragma unroll
            for (int i = 0; i < RMAX; i++)
                if (i < R) ok = ok && (ra[i] == ONE2) && (rb[i] == ONE2);
            if (w > 0)      ok = ok && (pa == ONE2) && (pb == ONE2);
            if (w < NW - 1) ok = ok && (na == ONE2) && (nb == ONE2);
            ok = ok || !lane_act;            // idle lanes don't veto
            skip = __all_sync(0xffffffffu, ok);
        }

        if (!skip) {
            #pragma unroll
            for (int i = 0; i < RMAX; i++) {
                if (i < R) {
                    const u64 ca = ra[i], cb = rb[i];
                    u64 xa = na, xb = nb;
                    if (i + 1 < RMAX) {
                        if (i + 1 < R) { xa = ra[i + 1]; xb = rb[i + 1]; }
                    }
                    const u64 lf = __shfl_up_sync(0xffffffffu, cb, 1);   // col 2pl-1
                    const u64 rt = __shfl_down_sync(0xffffffffu, ca, 1); // col 2pl+2

                    // out(2pl)   = lf + ca + cb + up_a + dn_a
                    // out(2pl+1) = ca + cb + rt + up_b + dn_b  (t = ca+cb shared)
                    u64 t, s0, s1;
                    ADD_F32X2(t, ca, cb);
                    ADD_F32X2(s0, t, lf);
                    ADD_F32X2(s0, s0, pa);
                    ADD_F32X2(s0, s0, xa);
                    ADD_F32X2(s1, t, rt);
                    ADD_F32X2(s1, s1, pb);
                    ADD_F32X2(s1, s1, xb);

                    float a0, a1, b0, b1;
                    UNPACK2(a0, a1, s0);
                    UNPACK2(b0, b1, s1);
                    a0 = fminf(a0, 1.0f); a1 = fminf(a1, 1.0f);
                    b0 = fminf(b0, 1.0f); b1 = fminf(b1, 1.0f);

                    if (!interior) {
                        // Re-zero out-of-image cells: reference zero-pads EVERY conv.
                        const bool rin = (unsigned)(y0 + r_lo + i) < H_IMG;
                        const bool in  = rin && col_in;
                        a0 = in ? a0 : 0.0f;  a1 = in ? a1 : 0.0f;
                        b0 = in ? b0 : 0.0f;  b1 = in ? b1 : 0.0f;
                    }

                    pa = ca; pb = cb;            // old row becomes "up" for next row
                    PACK2(ra[i], a0, a1);
                    PACK2(rb[i], b0, b1);
                }
            }
        }
        // one sync per iter is safe: next iteration stores to the other parity slot
    }

    // ---- BCE straight from registers ----
    // inner cols: local [6,54) <=> lanes 3..26; inner rows: local [5,37)
    float lsum = 0.0f;
    if (pl >= 3 && pl <= 26) {
        const float* tb = target + img;
        #pragma unroll
        for (int i = 0; i < RMAX; i++) {
            if (i < R) {
                const int rl = r_lo + i;
                if (rl >= HALO_Y && rl < HALO_Y + TILE_Y) {
                    const int gy = y0 + rl;
                    const float2 t2 = *(const float2*)(tb + gy * W_IMG + gx);
                    float h0, o0, h1, o1;
                    UNPACK2(h0, o0, ra[i]);
                    UNPACK2(h1, o1, rb[i]);
                    const float p0 = h0 * o0;
                    const float p1 = h1 * o1;
                    float c0, c1;
                    if (p0 >= 1.0f) c0 = -100.0f * (1.0f - t2.x);
                    else {
                        float lp  = fmaxf(logf(p0), -100.0f);
                        float l1p = fmaxf(logf(1.0f - p0), -100.0f);
                        c0 = t2.x * lp + (1.0f - t2.x) * l1p;
                    }
                    if (p1 >= 1.0f) c1 = -100.0f * (1.0f - t2.y);
                    else {
                        float lp  = fmaxf(logf(p1), -100.0f);
                        float l1p = fmaxf(logf(1.0f - p1), -100.0f);
                        c1 = t2.y * lp + (1.0f - t2.y) * l1p;
                    }
                    lsum += c0 + c1;
                }
            }
        }
    }

    // ---- Reduction ----
    #pragma unroll
    for (int off = 16; off > 0; off >>= 1)
        lsum += __shfl_down_sync(0xffffffffu, lsum, off);

    if (pl == 0) red[w] = lsum;
    __syncthreads();

    if (tid < NW) {
        float v = red[tid];
        #pragma unroll
        for (int off = NW / 2; off > 0; off >>= 1)
            v += __shfl_down_sync((1u << NW) - 1u, v, off);
        if (tid == 0) {
            const float inv_total = 1.0f / ((float)N_IMG * H_IMG * W_IMG);
            atomicAdd(out, -v * inv_total);
        }
    }
}

extern "C" void kernel_launch(void* const* d_in, const int* in_sizes, int n_in,
                              void* d_out, int out_size)
{
    const float* hand   = (const float*)d_in[0];
    const float* obj    = (const float*)d_in[1];
    const float* target = (const float*)d_in[2];
    float* out = (float*)d_out;

    zero_out_kernel<<<1, 1>>>(out);

    dim3 grid(W_IMG / TILE_X, H_IMG / TILE_Y, N_IMG);   // 8 x 12 x 64 = 6144 blocks
    boundary_bce_fused_kernel<<<grid, NTHREADS>>>(hand, obj, target, out);
}